// round 10
// baseline (speedup 1.0000x reference)
#include <cuda_runtime.h>
#include <stdint.h>

#define N_NODES   50000
#define N_EDGES   640000
#define HIDDEN    128
#define NUM_GRAPHS 50
#define EPS       1e-5f
#define STAT_NPB  64

// Contiguous scratch, zeroed with one cudaMemsetAsync (no allocations).
#define OFF_DEG    0                       // 50000 floats  = 200000 B
#define OFF_STAT   200000                  // 6400 floats   =  25600 B
#define OFF_STAT2  225600                  // 6400 floats   =  25600 B
#define OFF_CNT    251200                  // 50 ints       =    200 B
#define OFF_DONE   251400                  // 1 int
#define SCRATCH_BYTES 251408

__device__ __align__(256) unsigned char g_scratch[SCRATCH_BYTES];

#define G_DEG   ((float*)(g_scratch + OFF_DEG))
#define G_STAT  ((float*)(g_scratch + OFF_STAT))
#define G_STAT2 ((float*)(g_scratch + OFF_STAT2))
#define G_CNT   ((int*)  (g_scratch + OFF_CNT))
#define G_DONE  ((int*)  (g_scratch + OFF_DONE))

// Index dtype detect — ALWAYS probe edge_index (random values in [0,50000)).
// int64 values < 50000 have zero odd 32-bit words; int32 edge data has random
// odd words (P(all 8 zero) ~ (2e-5)^8 ~ 0). NEVER probe batch_ptr: it is
// sorted and its leading zeros alias the int64 pattern.
__device__ __forceinline__ int detect_is64(const void* ei)
{
    const int* p = (const int*)ei;
    int nz = 0;
    #pragma unroll
    for (int k = 0; k < 8; k++) nz |= p[2 * k + 1];
    return nz == 0;
}

__device__ __forceinline__ int load_idx(const void* p, int i, int is64, int hi)
{
    long long v = is64 ? ((const long long*)p)[i] : (long long)((const int*)p)[i];
    if (v < 0) v = 0;
    if (v > hi) v = hi;
    return (int)v;
}

__device__ __forceinline__ void red_add_v4(float* dst, float4 v)
{
    asm volatile("red.global.add.v4.f32 [%0], {%1,%2,%3,%4};"
                 :: "l"(dst), "f"(v.x), "f"(v.y), "f"(v.z), "f"(v.w) : "memory");
}

// ---------------- init+deg: out = node (float4 copy) AND deg[col] += ea ----------------
__global__ void k_init_deg(const float4* __restrict__ node, float4* __restrict__ out,
                           const void* __restrict__ ei, const float* __restrict__ ea)
{
    int64_t j = (int64_t)blockIdx.x * blockDim.x + threadIdx.x;
    out[j] = node[j];                           // exact grid (6250x256), no bounds check

    // degree slice: 103 edges per block covers 640k edges over 6250 blocks
    int e = blockIdx.x * 103 + threadIdx.x;
    if (threadIdx.x < 103 && e < N_EDGES) {
        int is64 = detect_is64(ei);
        int c = load_idx(ei, N_EDGES + e, is64, N_NODES - 1);
        atomicAdd(&G_DEG[c], ea[e]);
    }
}

// ---------------- scatter: out[col] += node[row]*w (warp/edge, v4 red, inline rsqrt) ----------------
__global__ void k_scatter(const float* __restrict__ node,
                          const void* __restrict__ ei,
                          const float* __restrict__ ea,
                          float* __restrict__ out)
{
    int is64 = detect_is64(ei);
    int lane = threadIdx.x & 31;
    int e = blockIdx.x * (blockDim.x >> 5) + (threadIdx.x >> 5);
    if (e >= N_EDGES) return;

    int r = load_idx(ei, e, is64, N_NODES - 1);
    int c = load_idx(ei, N_EDGES + e, is64, N_NODES - 1);
    float dr = G_DEG[r], dc = G_DEG[c];
    float ir = dr > 0.0f ? rsqrtf(dr) : 0.0f;
    float ic = dc > 0.0f ? rsqrtf(dc) : 0.0f;
    float w = ir * ea[e] * ic;

    float4 v = reinterpret_cast<const float4*>(node + (size_t)r * HIDDEN)[lane];
    v.x *= w; v.y *= w; v.z *= w; v.w *= w;
    red_add_v4(out + (size_t)c * HIDDEN + lane * 4, v);
}

// ---------------- stats (thread-per-channel) + fused meanvar (last block) ----------------
__global__ void k_stats(const float* __restrict__ out,
                        const void* __restrict__ batch_ptr,
                        const void* __restrict__ ei,          // dtype probe only
                        const float* __restrict__ mean_scale,
                        const float* __restrict__ weight)
{
    __shared__ int s_last;
    int is64 = detect_is64(ei);
    int ch = threadIdx.x;                // 0..127
    int n0 = blockIdx.x * STAT_NPB;
    int n1 = n0 + STAT_NPB;
    if (n1 > N_NODES) n1 = N_NODES;

    if (n0 < n1) {
        int   g   = load_idx(batch_ptr, n0, is64, NUM_GRAPHS - 1);
        float s   = 0.0f, s2 = 0.0f;
        int   run = 0;
        for (int n = n0; n < n1; n++) {
            int gn = load_idx(batch_ptr, n, is64, NUM_GRAPHS - 1);
            if (gn != g) {
                atomicAdd(&G_STAT[g * HIDDEN + ch], s);
                atomicAdd(&G_STAT2[g * HIDDEN + ch], s2);
                if (ch == 0) atomicAdd(&G_CNT[g], run);
                s = 0.0f; s2 = 0.0f; run = 0; g = gn;
            }
            float v = out[(size_t)n * HIDDEN + ch];
            s += v; s2 += v * v; run++;
        }
        atomicAdd(&G_STAT[g * HIDDEN + ch], s);
        atomicAdd(&G_STAT2[g * HIDDEN + ch], s2);
        if (ch == 0) atomicAdd(&G_CNT[g], run);
    }

    // last-block does meanvar: mu = mean*ms, A = rsqrt(var+eps)*weight
    __threadfence();
    if (threadIdx.x == 0)
        s_last = (atomicAdd(G_DONE, 1) == (int)gridDim.x - 1);
    __syncthreads();
    if (s_last) {
        for (int i = threadIdx.x; i < NUM_GRAPHS * HIDDEN; i += blockDim.x) {
            int g2 = i >> 7, c2 = i & 127;
            float cnt  = fmaxf((float)G_CNT[g2], 1.0f);
            float mean = G_STAT[i] / cnt;
            float e2   = G_STAT2[i] / cnt;
            float ms   = mean_scale[c2];
            float var  = fmaxf(e2 - mean * mean * ms * (2.0f - ms), 0.0f);
            G_STAT[i]  = mean * ms;
            G_STAT2[i] = rsqrtf(var + EPS) * weight[c2];
        }
    }
}

// ---------------- final: out = relu((h - mu) * A + bias), float4 ----------------
__global__ void k_final(float4* __restrict__ out,
                        const void* __restrict__ batch_ptr,
                        const void* __restrict__ ei,          // dtype probe only
                        const float4* __restrict__ bias4)
{
    int is64 = detect_is64(ei);
    int64_t j = (int64_t)blockIdx.x * blockDim.x + threadIdx.x;   // exact grid
    const float4* mu4 = (const float4*)G_STAT;
    const float4* A4  = (const float4*)G_STAT2;
    int n  = (int)(j >> 5);
    int c4 = (int)(j & 31);
    int g  = load_idx(batch_ptr, n, is64, NUM_GRAPHS - 1);
    float4 h  = out[j];
    float4 mu = mu4[g * 32 + c4];
    float4 A  = A4[g * 32 + c4];
    float4 b  = bias4[c4];
    h.x = fmaxf((h.x - mu.x) * A.x + b.x, 0.0f);
    h.y = fmaxf((h.y - mu.y) * A.y + b.y, 0.0f);
    h.z = fmaxf((h.z - mu.z) * A.z + b.z, 0.0f);
    h.w = fmaxf((h.w - mu.w) * A.w + b.w, 0.0f);
    out[j] = h;
}

extern "C" void kernel_launch(void* const* d_in, const int* in_sizes, int n_in,
                              void* d_out, int out_size)
{
    // Resolve inputs by element count.
    int idx_node = -1, idx_ei = -1, idx_ea = -1, idx_bp = -1;
    int idx128[3]; int n128 = 0;
    for (int i = 0; i < n_in; i++) {
        switch (in_sizes[i]) {
            case N_NODES * HIDDEN:  idx_node = i; break;
            case 2 * N_EDGES:       idx_ei   = i; break;
            case N_EDGES:           idx_ea   = i; break;
            case N_NODES:           idx_bp   = i; break;
            case HIDDEN:            if (n128 < 3) idx128[n128++] = i; break;
        }
    }
    int idx_w, idx_b, idx_ms;
    if (idx_node >= 0 && idx_bp >= 0 && idx_node > idx_bp) {
        idx_b = idx128[0]; idx_ms = idx128[1]; idx_w = idx128[2];   // alphabetical
    } else {
        idx_w = idx128[0]; idx_b = idx128[1]; idx_ms = idx128[2];   // declaration
    }

    const float* node       = (const float*)d_in[idx_node];
    const void*  edge_index = d_in[idx_ei];
    const float* edge_attr  = (const float*)d_in[idx_ea];
    const void*  batch_ptr  = d_in[idx_bp];
    const float* weight     = (const float*)d_in[idx_w];
    const float* bias       = (const float*)d_in[idx_b];
    const float* mean_scale = (const float*)d_in[idx_ms];
    float* out = (float*)d_out;

    // zero all scratch with one async memset (graph-capturable, no allocation)
    void* scratch_ptr = nullptr;
    cudaGetSymbolAddress(&scratch_ptr, g_scratch);
    cudaMemsetAsync(scratch_ptr, 0, SCRATCH_BYTES);

    // init copy + degree atomics fused (6250 x 256 exactly covers 1.6M float4)
    k_init_deg<<<6250, 256>>>((const float4*)node, (float4*)out,
                              edge_index, edge_attr);
    // scatter: 512 threads = 16 edges per block
    k_scatter<<<(N_EDGES + 15) / 16, 512>>>(node, edge_index, edge_attr, out);
    // stats + fused meanvar
    k_stats<<<(N_NODES + STAT_NPB - 1) / STAT_NPB, HIDDEN>>>(out, batch_ptr,
                                                             edge_index,
                                                             mean_scale, weight);
    // final (6250 x 256 exact)
    k_final<<<6250, 256>>>((float4*)out, batch_ptr, edge_index,
                           (const float4*)bias);
}

// round 11
// speedup vs baseline: 1.4016x; 1.4016x over previous
#include <cuda_runtime.h>
#include <stdint.h>

#define N_NODES   50000
#define N_EDGES   640000
#define HIDDEN    128
#define NUM_GRAPHS 50
#define EPS       1e-5f
#define NODES_PER_BLOCK 64

// Scratch (no allocations allowed)
__device__ float g_deg[N_NODES];                 // raw degree
__device__ float g_stat[NUM_GRAPHS * HIDDEN];    // sum, then mu = mean*mean_scale
__device__ float g_stat2[NUM_GRAPHS * HIDDEN];   // sumsq, then A = invstd*weight
__device__ int   g_cnt[NUM_GRAPHS];
__device__ int   g_is64;                         // 1 = int64 indices, 0 = int32

__device__ __forceinline__ int load_idx(const void* p, int i, int is64, int hi)
{
    long long v = is64 ? ((const long long*)p)[i] : (long long)((const int*)p)[i];
    if (v < 0) v = 0;
    if (v > hi) v = hi;
    return (int)v;
}

__device__ __forceinline__ void red_add_v4(float* dst, float4 v)
{
    asm volatile("red.global.add.v4.f32 [%0], {%1,%2,%3,%4};"
                 :: "l"(dst), "f"(v.x), "f"(v.y), "f"(v.z), "f"(v.w) : "memory");
}

// ---------------- init: out = node (float4), zero scratch, detect dtype ----------------
__global__ void k_init(const float4* __restrict__ node, float4* __restrict__ out,
                       const int* __restrict__ ei32)
{
    if (blockIdx.x == 0) {
        int nz = 0;
        for (int k = threadIdx.x; k < 4096; k += blockDim.x)
            if (ei32[2 * k + 1] != 0) nz = 1;
        int any = __syncthreads_count(nz);
        if (threadIdx.x == 0) g_is64 = (any == 0) ? 1 : 0;
    }
    int64_t total = (int64_t)N_NODES * HIDDEN / 4;
    int64_t stride = (int64_t)gridDim.x * blockDim.x;
    for (int64_t j = (int64_t)blockIdx.x * blockDim.x + threadIdx.x; j < total; j += stride) {
        out[j] = node[j];
        if (j < N_NODES) g_deg[j] = 0.0f;
        if (j < NUM_GRAPHS * HIDDEN) { g_stat[j] = 0.0f; g_stat2[j] = 0.0f; }
        if (j < NUM_GRAPHS) g_cnt[j] = 0;
    }
}

// ---------------- degree: deg[col] += edge_attr (4 edges/thread) ----------------
__global__ void k_deg(const void* __restrict__ ei, const float* __restrict__ ea)
{
    int is64 = g_is64;
    int base = (blockIdx.x * blockDim.x + threadIdx.x) * 4;
    #pragma unroll
    for (int k = 0; k < 4; k++) {
        int e = base + k;
        if (e < N_EDGES) {
            int c = load_idx(ei, N_EDGES + e, is64, N_NODES - 1);
            atomicAdd(&g_deg[c], ea[e]);
        }
    }
}

// ---------------- scatter: 2 edges per warp (MLP=2), v4 red, inline rsqrt ----------------
__global__ void k_scatter(const float* __restrict__ node,
                          const void* __restrict__ ei,
                          const float* __restrict__ ea,
                          float* __restrict__ out)
{
    int is64 = g_is64;
    int lane = threadIdx.x & 31;
    int w = blockIdx.x * (blockDim.x >> 5) + (threadIdx.x >> 5);
    int e0 = w * 2;
    if (e0 >= N_EDGES) return;
    int e1 = e0 + 1;
    bool has1 = (e1 < N_EDGES);

    int r0 = load_idx(ei, e0, is64, N_NODES - 1);
    int c0 = load_idx(ei, N_EDGES + e0, is64, N_NODES - 1);
    int r1 = has1 ? load_idx(ei, e1, is64, N_NODES - 1) : r0;
    int c1 = has1 ? load_idx(ei, N_EDGES + e1, is64, N_NODES - 1) : c0;

    float dr0 = g_deg[r0], dc0 = g_deg[c0];
    float dr1 = g_deg[r1], dc1 = g_deg[c1];
    float w0 = (dr0 > 0.0f ? rsqrtf(dr0) : 0.0f) * ea[e0] *
               (dc0 > 0.0f ? rsqrtf(dc0) : 0.0f);
    float w1 = has1 ? (dr1 > 0.0f ? rsqrtf(dr1) : 0.0f) * ea[e1] *
                      (dc1 > 0.0f ? rsqrtf(dc1) : 0.0f)
                    : 0.0f;

    float4 v0 = reinterpret_cast<const float4*>(node + (size_t)r0 * HIDDEN)[lane];
    float4 v1 = reinterpret_cast<const float4*>(node + (size_t)r1 * HIDDEN)[lane];
    v0.x *= w0; v0.y *= w0; v0.z *= w0; v0.w *= w0;
    red_add_v4(out + (size_t)c0 * HIDDEN + lane * 4, v0);
    if (has1) {
        v1.x *= w1; v1.y *= w1; v1.z *= w1; v1.w *= w1;
        red_add_v4(out + (size_t)c1 * HIDDEN + lane * 4, v1);
    }
}

// ---------------- stats: per-(graph,ch) sum & sumsq, register-accumulated ----------------
__global__ void k_stats(const float* __restrict__ out,
                        const void* __restrict__ batch_ptr)
{
    int is64 = g_is64;
    int ch = threadIdx.x;                       // 0..127
    int n0 = blockIdx.x * NODES_PER_BLOCK;
    int n1 = n0 + NODES_PER_BLOCK;
    if (n1 > N_NODES) n1 = N_NODES;
    if (n0 >= n1) return;

    int   g   = load_idx(batch_ptr, n0, is64, NUM_GRAPHS - 1);
    float s   = 0.0f, s2 = 0.0f;
    int   run = 0;

    for (int n = n0; n < n1; n++) {
        int gn = load_idx(batch_ptr, n, is64, NUM_GRAPHS - 1);
        if (gn != g) {
            atomicAdd(&g_stat[g * HIDDEN + ch], s);
            atomicAdd(&g_stat2[g * HIDDEN + ch], s2);
            if (ch == 0) atomicAdd(&g_cnt[g], run);
            s = 0.0f; s2 = 0.0f; run = 0; g = gn;
        }
        float v = out[(size_t)n * HIDDEN + ch];
        s += v; s2 += v * v; run++;
    }
    atomicAdd(&g_stat[g * HIDDEN + ch], s);
    atomicAdd(&g_stat2[g * HIDDEN + ch], s2);
    if (ch == 0) atomicAdd(&g_cnt[g], run);
}

// ---------------- meanvar: mu = mean*ms, A = rsqrt(var+eps)*weight ----------------
__global__ void k_meanvar(const float* __restrict__ mean_scale,
                          const float* __restrict__ weight)
{
    int i = blockIdx.x * blockDim.x + threadIdx.x;
    if (i < NUM_GRAPHS * HIDDEN) {
        int g = i >> 7, ch = i & 127;
        float cnt  = fmaxf((float)g_cnt[g], 1.0f);
        float mean = g_stat[i] / cnt;
        float e2   = g_stat2[i] / cnt;
        float ms   = mean_scale[ch];
        float var  = fmaxf(e2 - mean * mean * ms * (2.0f - ms), 0.0f);
        g_stat[i]  = mean * ms;
        g_stat2[i] = rsqrtf(var + EPS) * weight[ch];
    }
}

// ---------------- final: out = relu((h - mu) * A + bias), float4, exact grid ----------------
__global__ void k_final(float4* __restrict__ out,
                        const void* __restrict__ batch_ptr,
                        const float4* __restrict__ bias4)
{
    int is64 = g_is64;
    int64_t j = (int64_t)blockIdx.x * blockDim.x + threadIdx.x;
    if (j >= (int64_t)N_NODES * (HIDDEN / 4)) return;
    const float4* mu4 = (const float4*)g_stat;
    const float4* A4  = (const float4*)g_stat2;
    int n  = (int)(j >> 5);
    int c4 = (int)(j & 31);
    int g  = load_idx(batch_ptr, n, is64, NUM_GRAPHS - 1);
    float4 h  = out[j];
    float4 mu = mu4[g * 32 + c4];
    float4 A  = A4[g * 32 + c4];
    float4 b  = bias4[c4];
    h.x = fmaxf((h.x - mu.x) * A.x + b.x, 0.0f);
    h.y = fmaxf((h.y - mu.y) * A.y + b.y, 0.0f);
    h.z = fmaxf((h.z - mu.z) * A.z + b.z, 0.0f);
    h.w = fmaxf((h.w - mu.w) * A.w + b.w, 0.0f);
    out[j] = h;
}

extern "C" void kernel_launch(void* const* d_in, const int* in_sizes, int n_in,
                              void* d_out, int out_size)
{
    // Resolve inputs by element count.
    int idx_node = -1, idx_ei = -1, idx_ea = -1, idx_bp = -1;
    int idx128[3]; int n128 = 0;
    for (int i = 0; i < n_in; i++) {
        switch (in_sizes[i]) {
            case N_NODES * HIDDEN:  idx_node = i; break;
            case 2 * N_EDGES:       idx_ei   = i; break;
            case N_EDGES:           idx_ea   = i; break;
            case N_NODES:           idx_bp   = i; break;
            case HIDDEN:            if (n128 < 3) idx128[n128++] = i; break;
        }
    }
    int idx_w, idx_b, idx_ms;
    if (idx_node >= 0 && idx_bp >= 0 && idx_node > idx_bp) {
        idx_b = idx128[0]; idx_ms = idx128[1]; idx_w = idx128[2];   // alphabetical
    } else {
        idx_w = idx128[0]; idx_b = idx128[1]; idx_ms = idx128[2];   // declaration
    }

    const float* node       = (const float*)d_in[idx_node];
    const void*  edge_index = d_in[idx_ei];
    const float* edge_attr  = (const float*)d_in[idx_ea];
    const void*  batch_ptr  = d_in[idx_bp];
    const float* weight     = (const float*)d_in[idx_w];
    const float* bias       = (const float*)d_in[idx_b];
    const float* mean_scale = (const float*)d_in[idx_ms];
    float* out = (float*)d_out;

    const int64_t NH4 = (int64_t)N_NODES * HIDDEN / 4;   // 1,600,000

    // init + dtype detect
    {
        int threads = 256;
        int blocks = (int)((NH4 + threads - 1) / threads);
        if (blocks > 8192) blocks = 8192;
        k_init<<<blocks, threads>>>((const float4*)node, (float4*)out,
                                    (const int*)edge_index);
    }
    // degree (4 edges/thread)
    k_deg<<<(N_EDGES / 4 + 255) / 256, 256>>>(edge_index, edge_attr);
    // scatter: 512 threads = 16 warps = 32 edges per block
    k_scatter<<<(N_EDGES + 31) / 32, 512>>>(node, edge_index, edge_attr, out);
    // graphnorm
    k_stats<<<(N_NODES + NODES_PER_BLOCK - 1) / NODES_PER_BLOCK, HIDDEN>>>(out, batch_ptr);
    k_meanvar<<<(NUM_GRAPHS * HIDDEN + 255) / 256, 256>>>(mean_scale, weight);
    {
        int threads = 256;
        int blocks = (int)((NH4 + threads - 1) / threads);   // exact cover
        k_final<<<blocks, threads>>>((float4*)out, batch_ptr, (const float4*)bias);
    }
}

// round 12
// speedup vs baseline: 1.4879x; 1.0616x over previous
#include <cuda_runtime.h>
#include <stdint.h>

#define N_NODES   50000
#define N_EDGES   640000
#define HIDDEN    128
#define NUM_GRAPHS 50
#define EPS       1e-5f
#define NODES_PER_BLOCK 64

static_assert(N_EDGES % 4 == 0, "scatter assumes N_EDGES divisible by 4");

// Scratch (no allocations allowed)
__device__ float g_deg[N_NODES];                 // raw degree
__device__ float g_stat[NUM_GRAPHS * HIDDEN];    // sum, then mu = mean*mean_scale
__device__ float g_stat2[NUM_GRAPHS * HIDDEN];   // sumsq, then A = invstd*weight
__device__ int   g_cnt[NUM_GRAPHS];
__device__ int   g_is64;                         // 1 = int64 indices, 0 = int32

__device__ __forceinline__ int load_idx(const void* p, int i, int is64, int hi)
{
    long long v = is64 ? ((const long long*)p)[i] : (long long)((const int*)p)[i];
    if (v < 0) v = 0;
    if (v > hi) v = hi;
    return (int)v;
}

__device__ __forceinline__ void red_add_v4(float* dst, float4 v)
{
    asm volatile("red.global.add.v4.f32 [%0], {%1,%2,%3,%4};"
                 :: "l"(dst), "f"(v.x), "f"(v.y), "f"(v.z), "f"(v.w) : "memory");
}

// ---------------- init: out = node (float4), zero scratch, detect dtype ----------------
__global__ void k_init(const float4* __restrict__ node, float4* __restrict__ out,
                       const int* __restrict__ ei32)
{
    if (blockIdx.x == 0) {
        int nz = 0;
        for (int k = threadIdx.x; k < 4096; k += blockDim.x)
            if (ei32[2 * k + 1] != 0) nz = 1;
        int any = __syncthreads_count(nz);
        if (threadIdx.x == 0) g_is64 = (any == 0) ? 1 : 0;
    }
    int64_t total = (int64_t)N_NODES * HIDDEN / 4;
    int64_t stride = (int64_t)gridDim.x * blockDim.x;
    for (int64_t j = (int64_t)blockIdx.x * blockDim.x + threadIdx.x; j < total; j += stride) {
        out[j] = node[j];
        if (j < N_NODES) g_deg[j] = 0.0f;
        if (j < NUM_GRAPHS * HIDDEN) { g_stat[j] = 0.0f; g_stat2[j] = 0.0f; }
        if (j < NUM_GRAPHS) g_cnt[j] = 0;
    }
}

// ---------------- degree: deg[col] += edge_attr (4 edges/thread) ----------------
__global__ void k_deg(const void* __restrict__ ei, const float* __restrict__ ea)
{
    int is64 = g_is64;
    int base = (blockIdx.x * blockDim.x + threadIdx.x) * 4;
    #pragma unroll
    for (int k = 0; k < 4; k++) {
        int e = base + k;
        if (e < N_EDGES) {
            int c = load_idx(ei, N_EDGES + e, is64, N_NODES - 1);
            atomicAdd(&g_deg[c], ea[e]);
        }
    }
}

// ---------------- scatter: 4 edges per warp (MLP=4), v4 red, inline rsqrt ----------------
__global__ void k_scatter(const float* __restrict__ node,
                          const void* __restrict__ ei,
                          const float* __restrict__ ea,
                          float* __restrict__ out)
{
    int is64 = g_is64;
    int lane = threadIdx.x & 31;
    int w = blockIdx.x * (blockDim.x >> 5) + (threadIdx.x >> 5);
    int e0 = w * 4;
    if (e0 >= N_EDGES) return;     // N_EDGES % 4 == 0: all surviving warps are full

    int r[4], c[4];
    float wt[4];
    #pragma unroll
    for (int k = 0; k < 4; k++) {
        r[k] = load_idx(ei, e0 + k, is64, N_NODES - 1);
        c[k] = load_idx(ei, N_EDGES + e0 + k, is64, N_NODES - 1);
    }
    #pragma unroll
    for (int k = 0; k < 4; k++) {
        float dr = g_deg[r[k]], dc = g_deg[c[k]];
        float ir = dr > 0.0f ? rsqrtf(dr) : 0.0f;
        float ic = dc > 0.0f ? rsqrtf(dc) : 0.0f;
        wt[k] = ir * ea[e0 + k] * ic;
    }

    float4 v[4];
    #pragma unroll
    for (int k = 0; k < 4; k++)
        v[k] = reinterpret_cast<const float4*>(node + (size_t)r[k] * HIDDEN)[lane];
    #pragma unroll
    for (int k = 0; k < 4; k++) {
        v[k].x *= wt[k]; v[k].y *= wt[k]; v[k].z *= wt[k]; v[k].w *= wt[k];
        red_add_v4(out + (size_t)c[k] * HIDDEN + lane * 4, v[k]);
    }
}

// ---------------- stats: per-(graph,ch) sum & sumsq, register-accumulated ----------------
__global__ void k_stats(const float* __restrict__ out,
                        const void* __restrict__ batch_ptr)
{
    int is64 = g_is64;
    int ch = threadIdx.x;                       // 0..127
    int n0 = blockIdx.x * NODES_PER_BLOCK;
    int n1 = n0 + NODES_PER_BLOCK;
    if (n1 > N_NODES) n1 = N_NODES;
    if (n0 >= n1) return;

    int   g   = load_idx(batch_ptr, n0, is64, NUM_GRAPHS - 1);
    float s   = 0.0f, s2 = 0.0f;
    int   run = 0;

    for (int n = n0; n < n1; n++) {
        int gn = load_idx(batch_ptr, n, is64, NUM_GRAPHS - 1);
        if (gn != g) {
            atomicAdd(&g_stat[g * HIDDEN + ch], s);
            atomicAdd(&g_stat2[g * HIDDEN + ch], s2);
            if (ch == 0) atomicAdd(&g_cnt[g], run);
            s = 0.0f; s2 = 0.0f; run = 0; g = gn;
        }
        float v = out[(size_t)n * HIDDEN + ch];
        s += v; s2 += v * v; run++;
    }
    atomicAdd(&g_stat[g * HIDDEN + ch], s);
    atomicAdd(&g_stat2[g * HIDDEN + ch], s2);
    if (ch == 0) atomicAdd(&g_cnt[g], run);
}

// ---------------- meanvar: mu = mean*ms, A = rsqrt(var+eps)*weight ----------------
__global__ void k_meanvar(const float* __restrict__ mean_scale,
                          const float* __restrict__ weight)
{
    int i = blockIdx.x * blockDim.x + threadIdx.x;
    if (i < NUM_GRAPHS * HIDDEN) {
        int g = i >> 7, ch = i & 127;
        float cnt  = fmaxf((float)g_cnt[g], 1.0f);
        float mean = g_stat[i] / cnt;
        float e2   = g_stat2[i] / cnt;
        float ms   = mean_scale[ch];
        float var  = fmaxf(e2 - mean * mean * ms * (2.0f - ms), 0.0f);
        g_stat[i]  = mean * ms;
        g_stat2[i] = rsqrtf(var + EPS) * weight[ch];
    }
}

// ---------------- final: out = relu((h - mu) * A + bias), float4, exact grid ----------------
__global__ void k_final(float4* __restrict__ out,
                        const void* __restrict__ batch_ptr,
                        const float4* __restrict__ bias4)
{
    int is64 = g_is64;
    int64_t j = (int64_t)blockIdx.x * blockDim.x + threadIdx.x;
    if (j >= (int64_t)N_NODES * (HIDDEN / 4)) return;
    const float4* mu4 = (const float4*)g_stat;
    const float4* A4  = (const float4*)g_stat2;
    int n  = (int)(j >> 5);
    int c4 = (int)(j & 31);
    int g  = load_idx(batch_ptr, n, is64, NUM_GRAPHS - 1);
    float4 h  = out[j];
    float4 mu = mu4[g * 32 + c4];
    float4 A  = A4[g * 32 + c4];
    float4 b  = bias4[c4];
    h.x = fmaxf((h.x - mu.x) * A.x + b.x, 0.0f);
    h.y = fmaxf((h.y - mu.y) * A.y + b.y, 0.0f);
    h.z = fmaxf((h.z - mu.z) * A.z + b.z, 0.0f);
    h.w = fmaxf((h.w - mu.w) * A.w + b.w, 0.0f);
    out[j] = h;
}

extern "C" void kernel_launch(void* const* d_in, const int* in_sizes, int n_in,
                              void* d_out, int out_size)
{
    // Resolve inputs by element count.
    int idx_node = -1, idx_ei = -1, idx_ea = -1, idx_bp = -1;
    int idx128[3]; int n128 = 0;
    for (int i = 0; i < n_in; i++) {
        switch (in_sizes[i]) {
            case N_NODES * HIDDEN:  idx_node = i; break;
            case 2 * N_EDGES:       idx_ei   = i; break;
            case N_EDGES:           idx_ea   = i; break;
            case N_NODES:           idx_bp   = i; break;
            case HIDDEN:            if (n128 < 3) idx128[n128++] = i; break;
        }
    }
    int idx_w, idx_b, idx_ms;
    if (idx_node >= 0 && idx_bp >= 0 && idx_node > idx_bp) {
        idx_b = idx128[0]; idx_ms = idx128[1]; idx_w = idx128[2];   // alphabetical
    } else {
        idx_w = idx128[0]; idx_b = idx128[1]; idx_ms = idx128[2];   // declaration
    }

    const float* node       = (const float*)d_in[idx_node];
    const void*  edge_index = d_in[idx_ei];
    const float* edge_attr  = (const float*)d_in[idx_ea];
    const void*  batch_ptr  = d_in[idx_bp];
    const float* weight     = (const float*)d_in[idx_w];
    const float* bias       = (const float*)d_in[idx_b];
    const float* mean_scale = (const float*)d_in[idx_ms];
    float* out = (float*)d_out;

    const int64_t NH4 = (int64_t)N_NODES * HIDDEN / 4;   // 1,600,000

    // init + dtype detect
    {
        int threads = 256;
        int blocks = (int)((NH4 + threads - 1) / threads);
        if (blocks > 8192) blocks = 8192;
        k_init<<<blocks, threads>>>((const float4*)node, (float4*)out,
                                    (const int*)edge_index);
    }
    // degree (4 edges/thread)
    k_deg<<<(N_EDGES / 4 + 255) / 256, 256>>>(edge_index, edge_attr);
    // scatter: 512 threads = 16 warps = 64 edges per block
    k_scatter<<<(N_EDGES + 63) / 64, 512>>>(node, edge_index, edge_attr, out);
    // graphnorm
    k_stats<<<(N_NODES + NODES_PER_BLOCK - 1) / NODES_PER_BLOCK, HIDDEN>>>(out, batch_ptr);
    k_meanvar<<<(NUM_GRAPHS * HIDDEN + 255) / 256, 256>>>(mean_scale, weight);
    {
        int threads = 256;
        int blocks = (int)((NH4 + threads - 1) / threads);   // exact cover
        k_final<<<blocks, threads>>>((float4*)out, batch_ptr, (const float4*)bias);
    }
}